// round 14
// baseline (speedup 1.0000x reference)
#include <cuda_runtime.h>
#include <math.h>

// ---------------------------------------------------------------------------
// FourierBlock: rfft(L=4096) -> top-16 |X| per (b,c) -> mask -> irfft
// x: [B=64, L=4096, C=128] f32
//
// R13 base, restructured FFT: 2048 = 8 x 256 split.
//   forward: CTA-wide DIF radix-8 (gmem->regions) then per-WARP 256-pt FFT
//            (radix 8,8,4) in a private region -- __syncwarp only.
//   Z lives in "zpos" layout: Z[f] at region (f&7), pos (f>>3).
//   analysis: identical top-16 machinery, addresses via zpos.
//   inverse:  conj(Z') written at zpos (DIT-ready), per-warp 256-pt FFTs,
//             then CTA-wide combine (pre-twiddle + dft8) -> coalesced gmem.
// CTA barriers: 13 -> 9; 6 of 8 FFT passes warp-synchronous.
// ---------------------------------------------------------------------------

#define BATCH 64
#define LEN   4096
#define CH    128
#define NC    2048
#define NF    2049
#define TPB   256
#define NBINS 1024
#define CAP   1024

#define REGSTRIDE 273                      // region stride (float2), offsets bank phase
#define ZMAP(w,i) ((w) * REGSTRIDE + (i) + ((i) >> 4))
#define ZPOS(f)   ZMAP((f) & 7, (f) >> 3)
#define BUFSZ     (ZMAP(7, 255) + 8)       // 2189

#define HMAP(b) ((b) + ((b) >> 5))         // padded histogram index
#define HSZ    (HMAP(NBINS - 1) + 2)       // 1056

__device__ __align__(16) float g_scratch[BATCH * CH * LEN];
__device__ float2 g_tw[NC];                // cis(-2*pi*k/2048)
__device__ float2 g_twh[NF];               // H[f] = cis(-pi*f/2048)

// ------------------------------ warp redux ---------------------------------
__device__ __forceinline__ unsigned redux_max_u32(unsigned v) {
    unsigned r;
    asm("redux.sync.max.u32 %0, %1, 0xffffffff;" : "=r"(r) : "r"(v));
    return r;
}
__device__ __forceinline__ unsigned redux_min_u32(unsigned v) {
    unsigned r;
    asm("redux.sync.min.u32 %0, %1, 0xffffffff;" : "=r"(r) : "r"(v));
    return r;
}

// ------------------------------ complex helpers ----------------------------
__device__ __forceinline__ float2 cmul(float2 a, float2 b) {
    return make_float2(fmaf(a.x, b.x, -a.y * b.y), fmaf(a.x, b.y, a.y * b.x));
}
__device__ __forceinline__ float2 cadd(float2 a, float2 b) {
    return make_float2(a.x + b.x, a.y + b.y);
}
__device__ __forceinline__ float2 csub(float2 a, float2 b) {
    return make_float2(a.x - b.x, a.y - b.y);
}

__device__ __forceinline__ void dft4(float2 v[4]) {
    float2 t0 = cadd(v[0], v[2]);
    float2 t1 = csub(v[0], v[2]);
    float2 t2 = cadd(v[1], v[3]);
    float2 t3 = csub(v[1], v[3]);
    v[0] = cadd(t0, t2);
    v[2] = csub(t0, t2);
    v[1] = make_float2(t1.x + t3.y, t1.y - t3.x);
    v[3] = make_float2(t1.x - t3.y, t1.y + t3.x);
}

__device__ __forceinline__ void dft8(float2 v[8]) {
    float2 e[4] = { v[0], v[2], v[4], v[6] };
    float2 o[4] = { v[1], v[3], v[5], v[7] };
    dft4(e);
    dft4(o);
    const float s = 0.70710678118654752f;
    o[1] = make_float2(s * (o[1].x + o[1].y), s * (o[1].y - o[1].x));
    o[2] = make_float2(o[2].y, -o[2].x);
    o[3] = make_float2(s * (o[3].y - o[3].x), -s * (o[3].x + o[3].y));
#pragma unroll
    for (int k = 0; k < 4; k++) {
        v[k]     = cadd(e[k], o[k]);
        v[k + 4] = csub(e[k], o[k]);
    }
}

// ---------------------- global DIF pass (gmem -> regions) ------------------
// y[r][t] = (dft8 over n1 of x[t+256*n1]) * W_2048^{r*t} -> region r, pos t
__device__ __forceinline__ void pass1_fwd(const float2* __restrict__ gsrc,
                                          float2* __restrict__ dst, int t) {
    float2 v[8];
#pragma unroll
    for (int r = 0; r < 8; r++) v[r] = gsrc[t + r * 256];
    dft8(v);
#pragma unroll
    for (int r = 1; r < 8; r++) v[r] = cmul(v[r], __ldg(&g_tw[r * t]));
#pragma unroll
    for (int r = 0; r < 8; r++) dst[ZMAP(r, t)] = v[r];
}

// ---------------------- warp-local 256-pt FFT sub-passes -------------------
// sub-pass 1: radix-8, NS=1 (no twiddle)
__device__ __forceinline__ void sub8_1(const float2* __restrict__ src,
                                       float2* __restrict__ dst, int w, int lane) {
    float2 v[8];
#pragma unroll
    for (int r = 0; r < 8; r++) v[r] = src[ZMAP(w, lane + 32 * r)];
    dft8(v);
#pragma unroll
    for (int r = 0; r < 8; r++) dst[ZMAP(w, 8 * lane + r)] = v[r];
}

// sub-pass 2: radix-8, NS=8; twiddle W_64^{r*(lane&7)} = g_tw[32*(lane&7)*r]
__device__ __forceinline__ void sub8_2(const float2* __restrict__ src,
                                       float2* __restrict__ dst, int w, int lane) {
    float2 v[8];
#pragma unroll
    for (int r = 0; r < 8; r++) v[r] = src[ZMAP(w, lane + 32 * r)];
    int k = lane & 7;
#pragma unroll
    for (int r = 1; r < 8; r++) v[r] = cmul(v[r], __ldg(&g_tw[32 * k * r]));
    dft8(v);
    int idx = (lane >> 3) * 64 + k;
#pragma unroll
    for (int r = 0; r < 8; r++) dst[ZMAP(w, idx + 8 * r)] = v[r];
}

// sub-pass 3: radix-4, NS=64, in-place; twiddle W_256^{jj*r} = g_tw[8*jj*r]
__device__ __forceinline__ void sub4(float2* __restrict__ S, int w, int jj) {
    float2 v[4];
#pragma unroll
    for (int r = 0; r < 4; r++) v[r] = S[ZMAP(w, jj + 64 * r)];
#pragma unroll
    for (int r = 1; r < 4; r++) v[r] = cmul(v[r], __ldg(&g_tw[8 * jj * r]));
    dft4(v);
#pragma unroll
    for (int r = 0; r < 4; r++) S[ZMAP(w, jj + 64 * r)] = v[r];
}

// ---------------- global DIT combine (regions -> gmem, coalesced) ----------
// u[m+256j] = dft8_j( src[region f1][m] * W_2048^{f1*m} ); conj + 1/2048
__device__ __forceinline__ void combine_out(const float2* __restrict__ src,
                                            float2* __restrict__ gdst, int m) {
    float2 v[8];
#pragma unroll
    for (int f1 = 0; f1 < 8; f1++) v[f1] = src[ZMAP(f1, m)];
#pragma unroll
    for (int f1 = 1; f1 < 8; f1++) v[f1] = cmul(v[f1], __ldg(&g_tw[f1 * m]));
    dft8(v);
    const float inv = 1.0f / 2048.0f;
#pragma unroll
    for (int j = 0; j < 8; j++)
        gdst[m + 256 * j] = make_float2(v[j].x * inv, -v[j].y * inv);
}

// bin index for thread t, slot i
__device__ __forceinline__ int slot_bin(int t, int i) {
    return (i < 4) ? (t + (i << 8)) : ((i < 8) ? (2048 - (t + ((i - 4) << 8))) : 1024);
}

// ------------------------------ main kernel --------------------------------
__global__ void __launch_bounds__(TPB, 6) fourier_block_kernel() {
    __shared__ float2   bufA[BUFSZ];
    __shared__ float2   bufB[BUFSZ];
    __shared__ unsigned maskbits[65];
    __shared__ unsigned s_bcnt, s_T, s_cgt;

    // padded histogram + boundary candidates alias bufB (dead windows)
    unsigned* hist  = reinterpret_cast<unsigned*>(bufB);
    unsigned* candV = hist + HSZ;
    unsigned* candB = candV + CAP;

    const int tid  = threadIdx.x;
    const int lane = tid & 31;
    const int w    = tid >> 5;
    float2* series = reinterpret_cast<float2*>(g_scratch) + (size_t)blockIdx.x * NC;

    if (tid < 65) maskbits[tid] = 0u;
    if (tid == 0) s_bcnt = 0u;

    // ---------------- forward FFT ----------------
    pass1_fwd(series, bufA, tid);
    __syncthreads();                                   // bar1
    sub8_1(bufA, bufB, w, lane);
    __syncwarp();
    sub8_2(bufB, bufA, w, lane);
    __syncwarp();
    sub4(bufA, w, lane);
    sub4(bufA, w, lane + 32);
    __syncthreads();                                   // bar2: Z in bufA (zpos)

    // zero hist (aliases bufB; bufB dead after sub8_2 reads, fenced by bar2)
#pragma unroll
    for (int q = 0; q < 4; q++) hist[tid + (q << 8)] = 0u;
    if (tid < HSZ - 1024) hist[1024 + tid] = 0u;

    // ---------------- pairs pass 1: |X|^2 bits into registers ----------------
    unsigned fb[9];
#pragma unroll
    for (int q = 0; q < 4; q++) {
        int p = tid + (q << 8);
        float2 Zf = bufA[ZPOS(p)];
        float2 Zn = bufA[ZPOS((NC - p) & (NC - 1))];
        float2 S  = make_float2(Zf.x + Zn.x, Zf.y - Zn.y);
        float2 D  = make_float2(Zf.x - Zn.x, Zf.y + Zn.y);
        float2 H  = __ldg(&g_twh[p]);
        float2 T  = cmul(make_float2(-H.y, H.x), D);
        float2 XA = make_float2(S.x - T.x, S.y - T.y);
        float2 XB = make_float2(S.x + T.x, S.y + T.y);
        fb[q]     = __float_as_uint(fmaf(XA.x, XA.x, XA.y * XA.y));
        fb[q + 4] = __float_as_uint(fmaf(XB.x, XB.x, XB.y * XB.y));
    }
    fb[8] = 0u;
    if (tid == 0) {                                    // bin 1024 (self-pair)
        float2 Zf = bufA[ZPOS(1024)];
        float2 S  = make_float2(2.0f * Zf.x, 0.0f);
        float2 D  = make_float2(0.0f, 2.0f * Zf.y);
        float2 H  = __ldg(&g_twh[1024]);
        float2 T  = cmul(make_float2(-H.y, H.x), D);
        float2 XA = make_float2(S.x - T.x, S.y - T.y);
        fb[8] = __float_as_uint(fmaf(XA.x, XA.x, XA.y * XA.y));
    }
    const int nv = (tid == 0) ? 9 : 8;
    __syncthreads();                                   // bar3: hist zero visible

    for (int i = 0; i < nv; i++)
        atomicAdd(&hist[HMAP(fb[i] >> 22)], 1u);
    __syncthreads();                                   // bar4

    // -------- warp0: threshold bin T + count above (conflict-free) -----------
    if (w == 0) {
        int hi = (NBINS - 1) - lane * 32;
        unsigned s = 0;
        for (int b2 = 0; b2 < 32; b2++) s += hist[HMAP(hi - b2)];
        unsigned cum = s;
#pragma unroll
        for (int o = 1; o < 32; o <<= 1) {
            unsigned t2 = __shfl_up_sync(0xffffffffu, cum, o);
            if (lane >= o) cum += t2;
        }
        unsigned excl = cum - s;
        bool hit = (excl < 16u) && (excl + s >= 16u);
        unsigned hm = __ballot_sync(0xffffffffu, hit);
        int hl = __ffs(hm) - 1;
        if (lane == hl) {
            unsigned run = excl;
            int b = hi;
            while (run + hist[HMAP(b)] < 16u) { run += hist[HMAP(b)]; b--; }
            s_T = (unsigned)b;
            s_cgt = run;
        }
    }
    __syncthreads();                                   // bar5
    const unsigned T_ = s_T;

    // ---------------- classify ----------------
    for (int i = 0; i < nv; i++) {
        unsigned pf = fb[i] >> 22;
        if (pf > T_) {
            int bn = slot_bin(tid, i);
            atomicOr(&maskbits[bn >> 5], 1u << (bn & 31));
        } else if (pf == T_) {
            unsigned s2 = atomicAdd(&s_bcnt, 1u);
            if (s2 < CAP) {
                candV[s2] = fb[i];
                candB[s2] = (unsigned)slot_bin(tid, i);
            }
        }
    }
    __syncthreads();                                   // bar6

    // --- warp0: boundary refinement; warps 1-7 overlap definite-drop zeroing --
    unsigned dropmask = 0u;
    if (w == 0) {
        int need = 16 - (int)s_cgt;
        int m = (int)(s_bcnt < CAP ? s_bcnt : CAP);
        for (int it = 0; it < need; it++) {
            unsigned bv = 0u, bb = 0xFFFFFFFFu;
            for (int j = lane; j < m; j += 32) {
                unsigned v2 = candV[j], b2 = candB[j];
                if (v2 > bv || (v2 == bv && b2 < bb)) { bv = v2; bb = b2; }
            }
            unsigned best = redux_max_u32(bv);
            unsigned mb2 = (bv == best) ? bb : 0xFFFFFFFFu;
            unsigned wb = redux_min_u32(mb2);
            if (lane == 0) maskbits[wb >> 5] |= 1u << (wb & 31);
            for (int j = lane; j < m; j += 32)
                if (candB[j] == wb) candV[j] = 0u;
        }
    } else {
#pragma unroll
        for (int q = 0; q < 4; q++) {
            unsigned pfA = fb[q] >> 22;
            unsigned pfB = fb[q + 4] >> 22;
            if (pfA < T_ && pfB < T_) {
                int p = tid + (q << 8);
                bufA[ZPOS(p)] = make_float2(0.0f, 0.0f);
                bufA[ZPOS(2048 - p)] = make_float2(0.0f, 0.0f);
                dropmask |= 1u << q;
            }
        }
    }
    __syncthreads();                                   // bar7

    // ------- pairs pass 2: mask + inverse untangle, in place (zpos) -------
#pragma unroll
    for (int q = 0; q < 5; q++) {
        if (q < 4 && (dropmask >> q) & 1u) continue;
        int p = tid + (q << 8);
        if (q == 4 && tid != 0) break;
        if (q == 4) p = 1024;
        int binB = 2048 - p;
        unsigned ka = (maskbits[p >> 5] >> (p & 31)) & 1u;
        unsigned kb = (maskbits[binB >> 5] >> (binB & 31)) & 1u;
        if (!(ka | kb)) {
            bufA[ZPOS(p)] = make_float2(0.0f, 0.0f);
            if (p != 0 && p != 1024)
                bufA[ZPOS(binB)] = make_float2(0.0f, 0.0f);
            continue;
        }
        int pm = (NC - p) & (NC - 1);
        float2 Zf = bufA[ZPOS(p)];
        float2 Zn = bufA[ZPOS(pm)];
        float2 S  = make_float2(Zf.x + Zn.x, Zf.y - Zn.y);
        float2 D  = make_float2(Zf.x - Zn.x, Zf.y + Zn.y);
        float2 H  = __ldg(&g_twh[p]);
        float2 T  = cmul(make_float2(-H.y, H.x), D);
        float2 A  = ka ? make_float2(0.5f * (S.x - T.x), 0.5f * (S.y - T.y))
                       : make_float2(0.0f, 0.0f);
        float2 Bc = kb ? make_float2(0.5f * (S.x + T.x), 0.5f * (S.y + T.y))
                       : make_float2(0.0f, 0.0f);
        float2 St = make_float2(A.x + Bc.x, A.y + Bc.y);
        float2 Q  = make_float2(Bc.x - A.x, Bc.y - A.y);
        float2 Dt = cmul(make_float2(-H.y, -H.x), Q);
        bufA[ZPOS(p)] = make_float2(0.5f * (St.x + Dt.x), -0.5f * (St.y + Dt.y));
        if (p != 0 && p != 1024)
            bufA[ZPOS(binB)] = make_float2(0.5f * (St.x - Dt.x), 0.5f * (St.y - Dt.y));
    }
    __syncthreads();                                   // bar8

    // ---------------- inverse FFT (DIT): warp subs then combine ----------------
    sub8_1(bufA, bufB, w, lane);
    __syncwarp();
    sub8_2(bufB, bufA, w, lane);
    __syncwarp();
    sub4(bufA, w, lane);
    sub4(bufA, w, lane + 32);
    __syncthreads();                                   // bar9
    combine_out(bufA, series, tid);
}

// ------------------------------ twiddle init -------------------------------
__global__ void twiddle_init_kernel() {
    int k = blockIdx.x * blockDim.x + threadIdx.x;
    if (k < NC) {
        double s, c;
        sincospi(-(double)k / 1024.0, &s, &c);
        g_tw[k] = make_float2((float)c, (float)s);
    }
    if (k < NF) {
        double s, c;
        sincospi((double)k / 2048.0, &s, &c);
        g_twh[k] = make_float2((float)c, (float)(-s));
    }
}

// ------------------------------ transposes ---------------------------------
__global__ void __launch_bounds__(256) transpose_fwd_kernel(const float* __restrict__ x) {
    __shared__ float tile[32][129];
    const int b  = blockIdx.z;
    const int c0 = blockIdx.x * 32;
    const int l0 = blockIdx.y * 128;
    const float* xb = x + (size_t)b * LEN * CH;
    float* sb = g_scratch + (size_t)b * CH * LEN;
    const int lane = threadIdx.x & 31;
    const int wrp  = threadIdx.x >> 5;
#pragma unroll
    for (int k = 0; k < 16; k++) {
        int l = wrp + k * 8;
        tile[lane][l] = xb[(size_t)(l0 + l) * CH + (c0 + lane)];
    }
    __syncthreads();
#pragma unroll
    for (int m = 0; m < 4; m++) {
        int c = wrp * 4 + m;
        float4 v = make_float4(tile[c][4 * lane + 0], tile[c][4 * lane + 1],
                               tile[c][4 * lane + 2], tile[c][4 * lane + 3]);
        *reinterpret_cast<float4*>(&sb[(size_t)(c0 + c) * LEN + l0 + 4 * lane]) = v;
    }
}

__global__ void __launch_bounds__(256) transpose_bwd_kernel(float* __restrict__ out) {
    __shared__ float tile[32][129];
    const int b  = blockIdx.z;
    const int c0 = blockIdx.x * 32;
    const int l0 = blockIdx.y * 128;
    const float* sb = g_scratch + (size_t)b * CH * LEN;
    float* ob = out + (size_t)b * LEN * CH;
    const int lane = threadIdx.x & 31;
    const int wrp  = threadIdx.x >> 5;
#pragma unroll
    for (int m = 0; m < 4; m++) {
        int c = wrp * 4 + m;
        float4 v = *reinterpret_cast<const float4*>(
            &sb[(size_t)(c0 + c) * LEN + l0 + 4 * lane]);
        tile[c][4 * lane + 0] = v.x;
        tile[c][4 * lane + 1] = v.y;
        tile[c][4 * lane + 2] = v.z;
        tile[c][4 * lane + 3] = v.w;
    }
    __syncthreads();
#pragma unroll
    for (int k = 0; k < 16; k++) {
        int l = wrp + k * 8;
        ob[(size_t)(l0 + l) * CH + (c0 + lane)] = tile[lane][l];
    }
}

// ------------------------------ launch -------------------------------------
extern "C" void kernel_launch(void* const* d_in, const int* in_sizes, int n_in,
                              void* d_out, int out_size) {
    const float* x = (const float*)d_in[0];
    float* out = (float*)d_out;

    twiddle_init_kernel<<<65, 32>>>();
    transpose_fwd_kernel<<<dim3(CH / 32, LEN / 128, BATCH), 256>>>(x);
    fourier_block_kernel<<<BATCH * CH, TPB>>>();
    transpose_bwd_kernel<<<dim3(CH / 32, LEN / 128, BATCH), 256>>>(out);
}